// round 3
// baseline (speedup 1.0000x reference)
#include <cuda_runtime.h>
#include <cstdint>

#define NIMG 4
#define NLVL 5
#define MTOT 4768
#define NEGV (-1e9f)
#define NMS_THR 0.7f
#define SCLAMP 4.135166556742356f

__device__ __forceinline__ int hwa_of(int l) { return 196608 >> (2 * l); }
__device__ __forceinline__ int k_of(int l) { return (l == 4) ? 768 : 1000; }

__device__ __forceinline__ unsigned int fkey(float f) {
    unsigned int u = __float_as_uint(f);
    return (u & 0x80000000u) ? ~u : (u | 0x80000000u);
}
__device__ __forceinline__ float unkey(unsigned int key) {
    return __uint_as_float((key & 0x80000000u) ? (key & 0x7FFFFFFFu) : ~key);
}

// ---------------- scratch (device globals; no allocations) ----------------
__device__ float g_boxes[NIMG][MTOT][4];
__device__ float g_fscore[NIMG][MTOT];
__device__ unsigned char g_valid[NIMG][MTOT];
__device__ unsigned long long g_keptw[20][16];
__device__ unsigned long long g_mask[20][1000][16];

struct Ptrs {
    const float* logit[NLVL];
    const float* delta[NLVL];
    const float* anch[NLVL];
};

// ---------------- block scan helper (1024 threads, exclusive) -------------
__device__ __forceinline__ int scan1024(int v, int* total, int* sw) {
    __syncthreads();
    int lane = threadIdx.x & 31, w = threadIdx.x >> 5;
    int x = v;
#pragma unroll
    for (int d = 1; d < 32; d <<= 1) {
        int y = __shfl_up_sync(0xFFFFFFFFu, x, d);
        if (lane >= d) x += y;
    }
    if (lane == 31) sw[w] = x;
    __syncthreads();
    if (w == 0) {
        int ws = sw[lane], xx = ws;
#pragma unroll
        for (int d = 1; d < 32; d <<= 1) {
            int y = __shfl_up_sync(0xFFFFFFFFu, xx, d);
            if (lane >= d) xx += y;
        }
        sw[lane] = xx - ws;
        if (lane == 31) sw[32] = xx;
    }
    __syncthreads();
    *total = sw[32];
    return x - v + sw[w];
}

// ============ stage 1: per-problem hist+thresh+collect+sort+decode ========
__global__ __launch_bounds__(1024) void k_big(Ptrs P) {
    extern __shared__ unsigned long long sh[];  // 8192 u64 = 64KB
    __shared__ int sw[33];
    __shared__ unsigned int sb1, scnt;
    unsigned int* hist = (unsigned int*)sh;  // first 16KB, dead after thresh

    int p = blockIdx.x, n = p / NLVL, l = p % NLVL;
    int HWA = hwa_of(l), k = k_of(l);
    int t = threadIdx.x;

    for (int b = t; b < 4096; b += 1024) hist[b] = 0;
    if (t == 0) scnt = 0;
    __syncthreads();

    const float4* base = (const float4*)(P.logit[l] + (size_t)n * HWA);
    int n4 = HWA >> 2;

    // pass 1: histogram of top-12 key bits, MLP=8 batched loads
    for (int b0 = 0; b0 < n4; b0 += 8192) {
        float4 v[8];
#pragma unroll
        for (int q = 0; q < 8; q++) {
            int idx = b0 + q * 1024 + t;
            if (idx < n4) v[q] = base[idx];
        }
#pragma unroll
        for (int q = 0; q < 8; q++) {
            int idx = b0 + q * 1024 + t;
            if (idx < n4) {
                atomicAdd(&hist[fkey(v[q].x) >> 20], 1u);
                atomicAdd(&hist[fkey(v[q].y) >> 20], 1u);
                atomicAdd(&hist[fkey(v[q].z) >> 20], 1u);
                atomicAdd(&hist[fkey(v[q].w) >> 20], 1u);
            }
        }
    }
    __syncthreads();

    // threshold: highest bin b1 s.t. count of keys in bins >= b1 reaches k
    {
        unsigned int loc[4], s = 0;
#pragma unroll
        for (int q = 0; q < 4; q++) {
            loc[q] = hist[4095 - (t * 4 + q)];
            s += loc[q];
        }
        int tot;
        int ex = scan1024((int)s, &tot, sw);
        unsigned int target = (unsigned int)k;
        if ((unsigned)ex < target && (unsigned)ex + s >= target) {
            unsigned int cum = (unsigned)ex;
#pragma unroll
            for (int q = 0; q < 4; q++) {
                if (cum + loc[q] >= target) {
                    sb1 = 4095u - (unsigned int)(t * 4 + q);
                    break;
                }
                cum += loc[q];
            }
        }
    }
    __syncthreads();
    unsigned int b1 = sb1;

    // pass 2: collect candidates (L2-hot), overwrite hist region
    for (int b0 = 0; b0 < n4; b0 += 8192) {
        float4 v[8];
#pragma unroll
        for (int q = 0; q < 8; q++) {
            int idx = b0 + q * 1024 + t;
            if (idx < n4) v[q] = base[idx];
        }
#pragma unroll
        for (int q = 0; q < 8; q++) {
            int idx = b0 + q * 1024 + t;
            if (idx < n4) {
                float vv[4] = {v[q].x, v[q].y, v[q].z, v[q].w};
#pragma unroll
                for (int e = 0; e < 4; e++) {
                    unsigned int key = fkey(vv[e]);
                    if ((key >> 20) >= b1) {
                        unsigned int pos = atomicAdd(&scnt, 1u);
                        if (pos < 8192u) {
                            int j = 4 * idx + e;
                            sh[pos] = ~(((unsigned long long)key << 32) |
                                        (unsigned int)(~(unsigned int)j));
                        }
                    }
                }
            }
        }
    }
    __syncthreads();
    unsigned int cnt = min(scnt, 8192u);
    int size = 1024;
    while (size < (int)cnt) size <<= 1;
    for (int i = t; i < size; i += 1024)
        if (i >= (int)cnt) sh[i] = ~0ULL;

    // bitonic sort ascending (of inverted composites == score desc, idx asc)
    for (int s = 2; s <= size; s <<= 1) {
        for (int st = s >> 1; st > 0; st >>= 1) {
            __syncthreads();
            int half = size >> 1;
            for (int tt = t; tt < half; tt += 1024) {
                int a = 2 * tt - (tt & (st - 1));
                int b = a + st;
                bool asc = ((a & s) == 0);
                unsigned long long x = sh[a], y = sh[b];
                if ((x > y) == asc) { sh[a] = y; sh[b] = x; }
            }
        }
    }
    __syncthreads();

    // decode top-k inline
    if (t < k) {
        unsigned long long c = ~sh[t];
        unsigned int key = (unsigned int)(c >> 32);
        int j = (int)(~(unsigned int)c);
        int m = l * 1000 + t;
        const float* a = P.anch[l] + 4 * (size_t)j;
        const float* d = P.delta[l] + 4 * ((size_t)n * HWA + j);
        float ax1 = a[0], ay1 = a[1], ax2 = a[2], ay2 = a[3];
        float wa = __fsub_rn(ax2, ax1), ha = __fsub_rn(ay2, ay1);
        float cxa = __fadd_rn(ax1, __fmul_rn(0.5f, wa));
        float cya = __fadd_rn(ay1, __fmul_rn(0.5f, ha));
        float dx = d[0], dy = d[1], dw = d[2], dh = d[3];
        dw = fminf(dw, SCLAMP);
        dh = fminf(dh, SCLAMP);
        float cx = __fadd_rn(__fmul_rn(dx, wa), cxa);
        float cy = __fadd_rn(__fmul_rn(dy, ha), cya);
        float w = __fmul_rn(wa, expf(dw));
        float h = __fmul_rn(ha, expf(dh));
        float x1 = __fsub_rn(cx, __fmul_rn(0.5f, w));
        float y1 = __fsub_rn(cy, __fmul_rn(0.5f, h));
        float x2 = __fadd_rn(cx, __fmul_rn(0.5f, w));
        float y2 = __fadd_rn(cy, __fmul_rn(0.5f, h));
        x1 = fminf(fmaxf(x1, 0.f), 1024.f);
        y1 = fminf(fmaxf(y1, 0.f), 1024.f);
        x2 = fminf(fmaxf(x2, 0.f), 1024.f);
        y2 = fminf(fmaxf(y2, 0.f), 1024.f);
        float ww = __fsub_rn(x2, x1), hh = __fsub_rn(y2, y1);
        bool valid = (ww > 0.f) && (hh > 0.f);
        g_boxes[n][m][0] = x1;
        g_boxes[n][m][1] = y1;
        g_boxes[n][m][2] = x2;
        g_boxes[n][m][3] = y2;
        g_valid[n][m] = valid ? 1 : 0;
        g_fscore[n][m] = valid ? unkey(key) : NEGV;
    }
}

// ============ stage 2: suppression bitmask, thread = (row, 64-col word) ===
__global__ __launch_bounds__(256) void k_iou() {
    int p = blockIdx.y, n = p / NLVL, l = p % NLVL, k = k_of(l);
    int rb = blockIdx.x;
    if (rb * 16 >= k) return;
    __shared__ float sx1[1000], sy1[1000], sx2[1000], sy2[1000], sar[1000];
    float offc = (float)l * 2048.0f;
    int off = l * 1000;
    for (int i = threadIdx.x; i < k; i += 256) {
        float a = __fadd_rn(g_boxes[n][off + i][0], offc);
        float b = __fadd_rn(g_boxes[n][off + i][1], offc);
        float c = __fadd_rn(g_boxes[n][off + i][2], offc);
        float d = __fadd_rn(g_boxes[n][off + i][3], offc);
        sx1[i] = a; sy1[i] = b; sx2[i] = c; sy2[i] = d;
        sar[i] = __fmul_rn(__fsub_rn(c, a), __fsub_rn(d, b));
    }
    __syncthreads();
    int i = rb * 16 + (threadIdx.x >> 4);
    int w = threadIdx.x & 15;
    if (i >= k) return;
    float ax1 = sx1[i], ay1 = sy1[i], ax2 = sx2[i], ay2 = sy2[i], aa = sar[i];
    int j0 = w * 64;
    unsigned long long bits = 0;
    if (j0 < k) {
        int jend = min(j0 + 64, k);
        for (int j = max(j0, i + 1); j < jend; j++) {
            float lx = fmaxf(ax1, sx1[j]), ly = fmaxf(ay1, sy1[j]);
            float rx = fminf(ax2, sx2[j]), ry = fminf(ay2, sy2[j]);
            float w_ = fmaxf(__fsub_rn(rx, lx), 0.f);
            float h_ = fmaxf(__fsub_rn(ry, ly), 0.f);
            float inter = __fmul_rn(w_, h_);
            if (inter > 0.f) {
                float den =
                    __fadd_rn(__fsub_rn(__fadd_rn(aa, sar[j]), inter), 1e-9f);
                if (__fdiv_rn(inter, den) > NMS_THR) bits |= 1ULL << (j - j0);
            }
        }
    }
    g_mask[p][i][w] = bits;
}

// ============ stage 3: 1-warp serial sweep, shfl-free inner chain =========
__global__ __launch_bounds__(32) void k_sweep() {
    int p = blockIdx.x, n = p / NLVL, l = p % NLVL, k = k_of(l), off = l * 1000;
    int lane = threadIdx.x;
    unsigned long long removedown = 0;  // lane<16: canonical word `lane`
    unsigned long long cur = 0;         // replicated: word of current span
    unsigned long long bufA[8], bufB[8];
    int nspan = (k + 63) >> 6;
#pragma unroll
    for (int q = 0; q < 8; q++)
        bufA[q] = (lane < 16 && q < k) ? g_mask[p][q][lane] : 0ULL;
    for (int s = 0; s < nspan; s++) {
        int base = s * 64;
        bool v0 = (base + lane) < k && g_valid[n][off + base + lane];
        bool v1 = (base + 32 + lane) < k && g_valid[n][off + base + 32 + lane];
        unsigned int m0 = __ballot_sync(0xFFFFFFFFu, v0);
        unsigned int m1 = __ballot_sync(0xFFFFFFFFu, v1);
        unsigned long long validw = ((unsigned long long)m1 << 32) | m0;
        unsigned long long keptw = 0;
        for (int sub = 0; sub < 8; sub++) {
            int nb = base + sub * 8 + 8;
#pragma unroll
            for (int q = 0; q < 8; q++) {
                int ni = nb + q;
                bufB[q] = (lane < 16 && ni < k) ? g_mask[p][ni][lane] : 0ULL;
            }
#pragma unroll
            for (int q = 0; q < 8; q++) {
                int bit = sub * 8 + q;
                unsigned long long rc = __shfl_sync(0xFFFFFFFFu, bufA[q], s);
                bool keep = ((validw >> bit) & 1ULL) && !((cur >> bit) & 1ULL);
                if (keep) {
                    cur |= rc;
                    removedown |= bufA[q];
                    keptw |= 1ULL << bit;
                }
            }
#pragma unroll
            for (int q = 0; q < 8; q++) bufA[q] = bufB[q];
        }
        if (lane == 0) g_keptw[p][s] = keptw;
        cur = __shfl_sync(0xFFFFFFFFu, removedown, min(s + 1, 15));
    }
    for (int s = nspan + lane; s < 16; s += 32) g_keptw[p][s] = 0ULL;
}

// ============ stage 4: partition + 5-way merge + stable split + output ====
__global__ __launch_bounds__(1024) void k_fin(float* out) {
    extern __shared__ unsigned long long comp[];       // [MTOT] u64
    int* perm = (int*)(comp + MTOT);                   // [MTOT] int
    __shared__ int sw[33];
    int n = blockIdx.x, t = threadIdx.x;

    // phase A: per-level stable partition (valid first) of composites
    for (int l = 0; l < NLVL; l++) {
        int k = k_of(l), off = l * 1000;
        int flag = 0;
        unsigned long long c = 0;
        if (t < k) {
            flag = g_valid[n][off + t];
            unsigned int key = fkey(g_fscore[n][off + t]);
            c = ((unsigned long long)(~key) << 32) | (unsigned int)(off + t);
        }
        int tot;
        int r = scan1024(flag, &tot, sw);
        if (t < k) comp[off + (flag ? r : tot + (t - r))] = c;
    }
    __syncthreads();

    // phase B: 5-way merge by binary-search rank
    for (int e = t; e < MTOT; e += 1024) {
        int l = e / 1000;
        unsigned long long c = comp[e];
        int rank = e - l * 1000;
#pragma unroll
        for (int l2 = 0; l2 < NLVL; l2++) {
            if (l2 == l) continue;
            int bse = l2 * 1000, len = k_of(l2);
            int lo = 0, hi = len;
            while (lo < hi) {
                int mid = (lo + hi) >> 1;
                if (comp[bse + mid] < c) lo = mid + 1;
                else hi = mid;
            }
            rank += lo;
        }
        perm[rank] = (int)(unsigned int)(c & 0xFFFFFFFFULL);
    }
    __syncthreads();

    // phase C: stable partition by kept flag, emit first 1000
    int f[5], mloc[5], ls = 0;
#pragma unroll
    for (int q = 0; q < 5; q++) {
        int r = t * 5 + q;
        if (r < MTOT) {
            int m = perm[r];
            mloc[q] = m;
            int lvl = m / 1000, mm = m % 1000;
            f[q] = (int)((g_keptw[n * NLVL + lvl][mm >> 6] >> (mm & 63)) & 1ULL);
        } else {
            mloc[q] = 0;
            f[q] = 0;
        }
        ls += f[q];
    }
    int tot;
    int kr = scan1024(ls, &tot, sw);
#pragma unroll
    for (int q = 0; q < 5; q++) {
        int r = t * 5 + q;
        if (r < MTOT) {
            int pos = f[q] ? kr : tot + (r - kr);
            if (pos < 1000) {
                int m = mloc[q];
                out[((size_t)n * 1000 + pos) * 4 + 0] = g_boxes[n][m][0];
                out[((size_t)n * 1000 + pos) * 4 + 1] = g_boxes[n][m][1];
                out[((size_t)n * 1000 + pos) * 4 + 2] = g_boxes[n][m][2];
                out[((size_t)n * 1000 + pos) * 4 + 3] = g_boxes[n][m][3];
                out[NIMG * 1000 * 4 + (size_t)n * 1000 + pos] =
                    f[q] ? g_fscore[n][m] : NEGV;
            }
            kr += f[q];
        }
    }
}

// ---------------- host launcher ----------------
extern "C" void kernel_launch(void* const* d_in, const int* in_sizes, int n_in,
                              void* d_out, int out_size) {
    Ptrs P;
    bool interleaved = (n_in >= 2 && in_sizes[1] == 3145728);
    for (int l = 0; l < NLVL; l++) {
        if (interleaved) {
            P.logit[l] = (const float*)d_in[3 * l + 0];
            P.delta[l] = (const float*)d_in[3 * l + 1];
            P.anch[l] = (const float*)d_in[3 * l + 2];
        } else {
            P.logit[l] = (const float*)d_in[l];
            P.delta[l] = (const float*)d_in[5 + l];
            P.anch[l] = (const float*)d_in[10 + l];
        }
    }
    float* out = (float*)d_out;

    cudaFuncSetAttribute(k_big, cudaFuncAttributeMaxDynamicSharedMemorySize,
                         65536);
    cudaFuncSetAttribute(k_fin, cudaFuncAttributeMaxDynamicSharedMemorySize,
                         MTOT * 12);

    k_big<<<20, 1024, 65536>>>(P);
    k_iou<<<dim3(63, 20), 256>>>();
    k_sweep<<<20, 32>>>();
    k_fin<<<4, 1024, MTOT * 12>>>(out);
}

// round 4
// speedup vs baseline: 1.0395x; 1.0395x over previous
#include <cuda_runtime.h>
#include <cstdint>

#define NIMG 4
#define NLVL 5
#define MTOT 4768
#define NEGV (-1e9f)
#define NMS_THR 0.7f
#define SCLAMP 4.135166556742356f

__device__ __forceinline__ int hwa_of(int l) { return 196608 >> (2 * l); }
__device__ __forceinline__ int k_of(int l) { return (l == 4) ? 768 : 1000; }

__device__ __forceinline__ unsigned int fkey(float f) {
    unsigned int u = __float_as_uint(f);
    return (u & 0x80000000u) ? ~u : (u | 0x80000000u);
}
__device__ __forceinline__ float unkey(unsigned int key) {
    return __uint_as_float((key & 0x80000000u) ? (key & 0x7FFFFFFFu) : ~key);
}

// ---------------- scratch (device globals; no allocations) ----------------
__device__ unsigned int g_hist[20][4096];
__device__ unsigned int g_cnt[20];
__device__ unsigned int g_b1[20];
__device__ unsigned long long g_cand[20][8192];
__device__ float g_boxes[NIMG][MTOT][4];
__device__ float g_fscore[NIMG][MTOT];
__device__ unsigned char g_valid[NIMG][MTOT];
__device__ unsigned long long g_comp[NIMG][MTOT];
__device__ unsigned long long g_keptw[20][16];
__device__ unsigned long long g_mask[20][1000][16];

struct Ptrs {
    const float* logit[NLVL];
    const float* delta[NLVL];
    const float* anch[NLVL];
};

// ---------------- block scan helper (1024 threads, exclusive) -------------
__device__ __forceinline__ int scan1024(int v, int* total, int* sw) {
    __syncthreads();
    int lane = threadIdx.x & 31, w = threadIdx.x >> 5;
    int x = v;
#pragma unroll
    for (int d = 1; d < 32; d <<= 1) {
        int y = __shfl_up_sync(0xFFFFFFFFu, x, d);
        if (lane >= d) x += y;
    }
    if (lane == 31) sw[w] = x;
    __syncthreads();
    if (w == 0) {
        int ws = sw[lane], xx = ws;
#pragma unroll
        for (int d = 1; d < 32; d <<= 1) {
            int y = __shfl_up_sync(0xFFFFFFFFu, xx, d);
            if (lane >= d) xx += y;
        }
        sw[lane] = xx - ws;
        if (lane == 31) sw[32] = xx;
    }
    __syncthreads();
    *total = sw[32];
    return x - v + sw[w];
}

// ---------------- stage 0: zero histograms ----------------
__global__ void k_zero() {
    int i = blockIdx.x * blockDim.x + threadIdx.x;
    if (i < 20 * 4096) ((unsigned int*)g_hist)[i] = 0;
}

// ---------------- stage 1a: histogram of top-12 key bits (MLP=4) ----------
__global__ __launch_bounds__(256) void k_hist(Ptrs P) {
    int p = blockIdx.y, n = p / NLVL, l = p % NLVL;
    int HWA = hwa_of(l);
    int n4 = HWA >> 2;
    int s4 = blockIdx.x * 1024;
    if (s4 >= n4) return;
    __shared__ unsigned int h[4096];
    for (int b = threadIdx.x; b < 4096; b += 256) h[b] = 0;
    __syncthreads();
    const float4* base = (const float4*)(P.logit[l] + (size_t)n * HWA);
    float4 v[4];
    int idx[4];
#pragma unroll
    for (int q = 0; q < 4; q++) {
        idx[q] = s4 + q * 256 + threadIdx.x;
        if (idx[q] < n4) v[q] = base[idx[q]];
    }
#pragma unroll
    for (int q = 0; q < 4; q++) {
        if (idx[q] < n4) {
            atomicAdd(&h[fkey(v[q].x) >> 20], 1u);
            atomicAdd(&h[fkey(v[q].y) >> 20], 1u);
            atomicAdd(&h[fkey(v[q].z) >> 20], 1u);
            atomicAdd(&h[fkey(v[q].w) >> 20], 1u);
        }
    }
    __syncthreads();
    for (int b = threadIdx.x; b < 4096; b += 256) {
        unsigned int c = h[b];
        if (c) atomicAdd(&g_hist[p][b], c);
    }
}

// ---------------- stage 1b: find 12-bit threshold bin ----------------
__global__ __launch_bounds__(256) void k_thresh() {
    int p = blockIdx.x, l = p % NLVL;
    unsigned int target = (unsigned int)k_of(l);
    int t = threadIdx.x;
    unsigned int loc[16], s = 0;
#pragma unroll
    for (int q = 0; q < 16; q++) {
        loc[q] = g_hist[p][4095 - (t * 16 + q)];
        s += loc[q];
    }
    __shared__ unsigned int wb[8];
    int lane = t & 31, w = t >> 5;
    unsigned int x = s;
#pragma unroll
    for (int d = 1; d < 32; d <<= 1) {
        unsigned int y = __shfl_up_sync(0xFFFFFFFFu, x, d);
        if (lane >= d) x += y;
    }
    if (lane == 31) wb[w] = x;
    __syncthreads();
    if (w == 0 && lane < 8) {
        unsigned int ws = wb[lane], xx = ws;
#pragma unroll
        for (int d = 1; d < 8; d <<= 1) {
            unsigned int y = __shfl_up_sync(0xFFu, xx, d);
            if (lane >= d) xx += y;
        }
        wb[lane] = xx - ws;
    }
    __syncthreads();
    unsigned int ex = x - s + wb[w];
    if (ex < target && ex + s >= target) {
        unsigned int cum = ex;
#pragma unroll
        for (int q = 0; q < 16; q++) {
            if (cum + loc[q] >= target) {
                g_b1[p] = 4095u - (unsigned int)(t * 16 + q);
                g_cnt[p] = 0u;
                break;
            }
            cum += loc[q];
        }
    }
}

// ---------------- stage 1c: collect candidates (MLP=4, L2-hot) ------------
__global__ __launch_bounds__(256) void k_collect(Ptrs P) {
    int p = blockIdx.y, n = p / NLVL, l = p % NLVL;
    int HWA = hwa_of(l);
    int n4 = HWA >> 2;
    int s4 = blockIdx.x * 1024;
    if (s4 >= n4) return;
    unsigned int b1 = g_b1[p];
    const float4* base = (const float4*)(P.logit[l] + (size_t)n * HWA);
    float4 v[4];
    int idx[4];
#pragma unroll
    for (int q = 0; q < 4; q++) {
        idx[q] = s4 + q * 256 + threadIdx.x;
        if (idx[q] < n4) v[q] = base[idx[q]];
    }
#pragma unroll
    for (int q = 0; q < 4; q++) {
        if (idx[q] < n4) {
            float vv[4] = {v[q].x, v[q].y, v[q].z, v[q].w};
#pragma unroll
            for (int e = 0; e < 4; e++) {
                unsigned int key = fkey(vv[e]);
                if ((key >> 20) >= b1) {
                    unsigned int pos = atomicAdd(&g_cnt[p], 1u);
                    if (pos < 8192u) {
                        int j = 4 * idx[q] + e;
                        g_cand[p][pos] = ((unsigned long long)key << 32) |
                                         (unsigned int)(~(unsigned int)j);
                    }
                }
            }
        }
    }
}

// ============ stage 2: sort + decode + partition (per (n,l) block) ========
__global__ __launch_bounds__(1024) void k_select(Ptrs P) {
    extern __shared__ unsigned long long sh[];
    __shared__ int sw[33];
    int p = blockIdx.x, n = p / NLVL, l = p % NLVL, k = k_of(l);
    int HWA = hwa_of(l), off = l * 1000;
    int t = threadIdx.x;
    unsigned int cnt = min(g_cnt[p], 8192u);
    int size = 1024;
    while (size < (int)cnt) size <<= 1;
    for (int i = t; i < size; i += 1024)
        sh[i] = (i < (int)cnt) ? ~g_cand[p][i] : ~0ULL;

    for (int s = 2; s <= size; s <<= 1) {
        for (int st = s >> 1; st > 0; st >>= 1) {
            __syncthreads();
            int half = size >> 1;
            for (int tt = t; tt < half; tt += 1024) {
                int a = 2 * tt - (tt & (st - 1));
                int b = a + st;
                bool asc = ((a & s) == 0);
                unsigned long long x = sh[a], y = sh[b];
                if ((x > y) == asc) { sh[a] = y; sh[b] = x; }
            }
        }
    }
    __syncthreads();

    // decode top-k inline; compute final score/valid
    int flag = 0;
    unsigned long long c = 0;
    if (t < k) {
        unsigned long long cc = ~sh[t];
        unsigned int key = (unsigned int)(cc >> 32);
        int j = (int)(~(unsigned int)cc);
        int m = off + t;
        const float* a = P.anch[l] + 4 * (size_t)j;
        const float* d = P.delta[l] + 4 * ((size_t)n * HWA + j);
        float ax1 = a[0], ay1 = a[1], ax2 = a[2], ay2 = a[3];
        float wa = __fsub_rn(ax2, ax1), ha = __fsub_rn(ay2, ay1);
        float cxa = __fadd_rn(ax1, __fmul_rn(0.5f, wa));
        float cya = __fadd_rn(ay1, __fmul_rn(0.5f, ha));
        float dx = d[0], dy = d[1], dw = d[2], dh = d[3];
        dw = fminf(dw, SCLAMP);
        dh = fminf(dh, SCLAMP);
        float cx = __fadd_rn(__fmul_rn(dx, wa), cxa);
        float cy = __fadd_rn(__fmul_rn(dy, ha), cya);
        float w = __fmul_rn(wa, expf(dw));
        float h = __fmul_rn(ha, expf(dh));
        float x1 = __fsub_rn(cx, __fmul_rn(0.5f, w));
        float y1 = __fsub_rn(cy, __fmul_rn(0.5f, h));
        float x2 = __fadd_rn(cx, __fmul_rn(0.5f, w));
        float y2 = __fadd_rn(cy, __fmul_rn(0.5f, h));
        x1 = fminf(fmaxf(x1, 0.f), 1024.f);
        y1 = fminf(fmaxf(y1, 0.f), 1024.f);
        x2 = fminf(fmaxf(x2, 0.f), 1024.f);
        y2 = fminf(fmaxf(y2, 0.f), 1024.f);
        float ww = __fsub_rn(x2, x1), hh = __fsub_rn(y2, y1);
        bool valid = (ww > 0.f) && (hh > 0.f);
        float sc = valid ? unkey(key) : NEGV;
        g_boxes[n][m][0] = x1;
        g_boxes[n][m][1] = y1;
        g_boxes[n][m][2] = x2;
        g_boxes[n][m][3] = y2;
        g_valid[n][m] = valid ? 1 : 0;
        g_fscore[n][m] = sc;
        flag = valid ? 1 : 0;
        c = ((unsigned long long)(~fkey(sc)) << 32) | (unsigned int)m;
    }
    // per-level stable partition (valid first) -> globally sorted per level
    int tot;
    int r = scan1024(flag, &tot, sw);
    if (t < k) g_comp[n][off + (flag ? r : tot + (t - r))] = c;
}

// ============ stage 3: suppression bitmask, thread = (row, 64-col word) ===
__global__ __launch_bounds__(256) void k_iou() {
    int p = blockIdx.y, n = p / NLVL, l = p % NLVL, k = k_of(l);
    int rb = blockIdx.x;
    if (rb * 16 >= k) return;
    __shared__ float sx1[1000], sy1[1000], sx2[1000], sy2[1000], sar[1000];
    float offc = (float)l * 2048.0f;
    int off = l * 1000;
    for (int i = threadIdx.x; i < k; i += 256) {
        float a = __fadd_rn(g_boxes[n][off + i][0], offc);
        float b = __fadd_rn(g_boxes[n][off + i][1], offc);
        float c = __fadd_rn(g_boxes[n][off + i][2], offc);
        float d = __fadd_rn(g_boxes[n][off + i][3], offc);
        sx1[i] = a; sy1[i] = b; sx2[i] = c; sy2[i] = d;
        sar[i] = __fmul_rn(__fsub_rn(c, a), __fsub_rn(d, b));
    }
    __syncthreads();
    int i = rb * 16 + (threadIdx.x >> 4);
    int w = threadIdx.x & 15;
    if (i >= k) return;
    float ax1 = sx1[i], ay1 = sy1[i], ax2 = sx2[i], ay2 = sy2[i], aa = sar[i];
    int j0 = w * 64;
    unsigned long long bits = 0;
    if (j0 < k) {
        int jend = min(j0 + 64, k);
        for (int j = max(j0, i + 1); j < jend; j++) {
            float lx = fmaxf(ax1, sx1[j]), ly = fmaxf(ay1, sy1[j]);
            float rx = fminf(ax2, sx2[j]), ry = fminf(ay2, sy2[j]);
            float w_ = fmaxf(__fsub_rn(rx, lx), 0.f);
            float h_ = fmaxf(__fsub_rn(ry, ly), 0.f);
            float inter = __fmul_rn(w_, h_);
            if (inter > 0.f) {
                float den =
                    __fadd_rn(__fsub_rn(__fadd_rn(aa, sar[j]), inter), 1e-9f);
                if (__fdiv_rn(inter, den) > NMS_THR) bits |= 1ULL << (j - j0);
            }
        }
    }
    g_mask[p][i][w] = bits;
}

// ============ stage 4: 1-warp serial sweep, shfl-free inner chain =========
__global__ __launch_bounds__(32) void k_sweep() {
    int p = blockIdx.x, n = p / NLVL, l = p % NLVL, k = k_of(l), off = l * 1000;
    int lane = threadIdx.x;
    unsigned long long removedown = 0;  // lane<16: canonical word `lane`
    unsigned long long cur = 0;         // replicated: word of current span
    unsigned long long bufA[8], bufB[8];
    int nspan = (k + 63) >> 6;
#pragma unroll
    for (int q = 0; q < 8; q++)
        bufA[q] = (lane < 16 && q < k) ? g_mask[p][q][lane] : 0ULL;
    for (int s = 0; s < nspan; s++) {
        int base = s * 64;
        bool v0 = (base + lane) < k && g_valid[n][off + base + lane];
        bool v1 = (base + 32 + lane) < k && g_valid[n][off + base + 32 + lane];
        unsigned int m0 = __ballot_sync(0xFFFFFFFFu, v0);
        unsigned int m1 = __ballot_sync(0xFFFFFFFFu, v1);
        unsigned long long validw = ((unsigned long long)m1 << 32) | m0;
        unsigned long long keptw = 0;
        for (int sub = 0; sub < 8; sub++) {
            int nb = base + sub * 8 + 8;
#pragma unroll
            for (int q = 0; q < 8; q++) {
                int ni = nb + q;
                bufB[q] = (lane < 16 && ni < k) ? g_mask[p][ni][lane] : 0ULL;
            }
#pragma unroll
            for (int q = 0; q < 8; q++) {
                int bit = sub * 8 + q;
                unsigned long long rc = __shfl_sync(0xFFFFFFFFu, bufA[q], s);
                bool keep = ((validw >> bit) & 1ULL) && !((cur >> bit) & 1ULL);
                if (keep) {
                    cur |= rc;
                    removedown |= bufA[q];
                    keptw |= 1ULL << bit;
                }
            }
#pragma unroll
            for (int q = 0; q < 8; q++) bufA[q] = bufB[q];
        }
        if (lane == 0) g_keptw[p][s] = keptw;
        cur = __shfl_sync(0xFFFFFFFFu, removedown, min(s + 1, 15));
    }
    for (int s = nspan + lane; s < 16; s += 32) g_keptw[p][s] = 0ULL;
}

// ============ stage 5: 5-way merge + stable split + output ================
__global__ __launch_bounds__(1024) void k_fin(float* out) {
    extern __shared__ unsigned long long comp[];  // [MTOT] u64
    int* perm = (int*)(comp + MTOT);              // [MTOT] int
    __shared__ int sw[33];
    int n = blockIdx.x, t = threadIdx.x;

    for (int e = t; e < MTOT; e += 1024) comp[e] = g_comp[n][e];
    __syncthreads();

    // 5-way merge by binary-search rank (each level list is sorted asc)
    for (int e = t; e < MTOT; e += 1024) {
        int l = e / 1000;
        unsigned long long c = comp[e];
        int rank = e - l * 1000;
#pragma unroll
        for (int l2 = 0; l2 < NLVL; l2++) {
            if (l2 == l) continue;
            int bse = l2 * 1000, len = k_of(l2);
            int lo = 0, hi = len;
            while (lo < hi) {
                int mid = (lo + hi) >> 1;
                if (comp[bse + mid] < c) lo = mid + 1;
                else hi = mid;
            }
            rank += lo;
        }
        perm[rank] = (int)(unsigned int)(c & 0xFFFFFFFFULL);
    }
    __syncthreads();

    // stable partition by kept flag, emit first 1000
    int f[5], mloc[5], ls = 0;
#pragma unroll
    for (int q = 0; q < 5; q++) {
        int r = t * 5 + q;
        if (r < MTOT) {
            int m = perm[r];
            mloc[q] = m;
            int lvl = m / 1000, mm = m % 1000;
            f[q] = (int)((g_keptw[n * NLVL + lvl][mm >> 6] >> (mm & 63)) & 1ULL);
        } else {
            mloc[q] = 0;
            f[q] = 0;
        }
        ls += f[q];
    }
    int tot;
    int kr = scan1024(ls, &tot, sw);
#pragma unroll
    for (int q = 0; q < 5; q++) {
        int r = t * 5 + q;
        if (r < MTOT) {
            int pos = f[q] ? kr : tot + (r - kr);
            if (pos < 1000) {
                int m = mloc[q];
                out[((size_t)n * 1000 + pos) * 4 + 0] = g_boxes[n][m][0];
                out[((size_t)n * 1000 + pos) * 4 + 1] = g_boxes[n][m][1];
                out[((size_t)n * 1000 + pos) * 4 + 2] = g_boxes[n][m][2];
                out[((size_t)n * 1000 + pos) * 4 + 3] = g_boxes[n][m][3];
                out[NIMG * 1000 * 4 + (size_t)n * 1000 + pos] =
                    f[q] ? g_fscore[n][m] : NEGV;
            }
            kr += f[q];
        }
    }
}

// ---------------- host launcher ----------------
extern "C" void kernel_launch(void* const* d_in, const int* in_sizes, int n_in,
                              void* d_out, int out_size) {
    Ptrs P;
    bool interleaved = (n_in >= 2 && in_sizes[1] == 3145728);
    for (int l = 0; l < NLVL; l++) {
        if (interleaved) {
            P.logit[l] = (const float*)d_in[3 * l + 0];
            P.delta[l] = (const float*)d_in[3 * l + 1];
            P.anch[l] = (const float*)d_in[3 * l + 2];
        } else {
            P.logit[l] = (const float*)d_in[l];
            P.delta[l] = (const float*)d_in[5 + l];
            P.anch[l] = (const float*)d_in[10 + l];
        }
    }
    float* out = (float*)d_out;

    cudaFuncSetAttribute(k_select, cudaFuncAttributeMaxDynamicSharedMemorySize,
                         65536);
    cudaFuncSetAttribute(k_fin, cudaFuncAttributeMaxDynamicSharedMemorySize,
                         MTOT * 12);

    k_zero<<<80, 1024>>>();
    k_hist<<<dim3(48, 20), 256>>>(P);
    k_thresh<<<20, 256>>>();
    k_collect<<<dim3(48, 20), 256>>>(P);
    k_select<<<20, 1024, 65536>>>(P);
    k_iou<<<dim3(63, 20), 256>>>();
    k_sweep<<<20, 32>>>();
    k_fin<<<4, 1024, MTOT * 12>>>(out);
}

// round 5
// speedup vs baseline: 1.0841x; 1.0429x over previous
#include <cuda_runtime.h>
#include <cstdint>

#define NIMG 4
#define NLVL 5
#define MTOT 4768
#define NEGV (-1e9f)
#define NMS_THR 0.7f
#define SCLAMP 4.135166556742356f
#define NBLK 148

__device__ __forceinline__ int hwa_of(int l) { return 196608 >> (2 * l); }
__device__ __forceinline__ int k_of(int l) { return (l == 4) ? 768 : 1000; }

__device__ __forceinline__ unsigned int fkey(float f) {
    unsigned int u = __float_as_uint(f);
    return (u & 0x80000000u) ? ~u : (u | 0x80000000u);
}
__device__ __forceinline__ float unkey(unsigned int key) {
    return __uint_as_float((key & 0x80000000u) ? (key & 0x7FFFFFFFu) : ~key);
}

// ---------------- scratch (device globals; no allocations) ----------------
__device__ unsigned int g_hist[20][4096];
__device__ unsigned int g_cnt[20];
__device__ unsigned int g_b1[20];
__device__ unsigned long long g_cand[20][8192];
__device__ float g_boxes[NIMG][MTOT][4];
__device__ float g_fscore[NIMG][MTOT];
__device__ unsigned char g_valid[NIMG][MTOT];
__device__ unsigned long long g_comp[NIMG][MTOT];
__device__ unsigned long long g_keptw[20][16];
__device__ unsigned long long g_mask[20][1000][16];
__device__ int g_permF[NIMG][MTOT];
__device__ unsigned long long g_barcnt[8];  // monotonic; NEVER reset (replay-safe)

struct Ptrs {
    const float* logit[NLVL];
    const float* delta[NLVL];
    const float* anch[NLVL];
};

// ---------------- replay-safe grid barrier (monotonic tickets) ------------
__device__ __forceinline__ void gridbar(int b) {
    __syncthreads();
    if (threadIdx.x == 0) {
        __threadfence();
        unsigned long long ticket = atomicAdd(&g_barcnt[b], 1ULL);
        unsigned long long target =
            (ticket / (unsigned long long)NBLK + 1ULL) * (unsigned long long)NBLK;
        while (((volatile unsigned long long*)g_barcnt)[b] < target) {
            __nanosleep(64);
        }
        __threadfence();
    }
    __syncthreads();
}

// ---------------- block scan helper (1024 threads, exclusive) -------------
__device__ __forceinline__ int scan1024(int v, int* total, int* sw) {
    __syncthreads();
    int lane = threadIdx.x & 31, w = threadIdx.x >> 5;
    int x = v;
#pragma unroll
    for (int d = 1; d < 32; d <<= 1) {
        int y = __shfl_up_sync(0xFFFFFFFFu, x, d);
        if (lane >= d) x += y;
    }
    if (lane == 31) sw[w] = x;
    __syncthreads();
    if (w == 0) {
        int ws = sw[lane], xx = ws;
#pragma unroll
        for (int d = 1; d < 32; d <<= 1) {
            int y = __shfl_up_sync(0xFFFFFFFFu, xx, d);
            if (lane >= d) xx += y;
        }
        sw[lane] = xx - ws;
        if (lane == 31) sw[32] = xx;
    }
    __syncthreads();
    *total = sw[32];
    return x - v + sw[w];
}

// chunk index -> (n, l, c); 34 chunks of 8192 elems per image, 136 total
__device__ __forceinline__ void chunk_map(int ci, int& n, int& l, int& c) {
    n = ci / 34;
    int r = ci % 34;
    if (r < 24) { l = 0; c = r; }
    else if (r < 30) { l = 1; c = r - 24; }
    else if (r < 32) { l = 2; c = r - 30; }
    else if (r < 33) { l = 3; c = 0; }
    else { l = 4; c = 0; }
}

// ============================ the one kernel ==============================
__global__ void __launch_bounds__(1024, 1) k_all(Ptrs P, float* out) {
    extern __shared__ unsigned char smem_raw[];
    __shared__ int sw[33];
    int bid = blockIdx.x, t = threadIdx.x;

    // ---- S0: zero global histograms ----
    {
        unsigned int* H = (unsigned int*)g_hist;
        for (int i = bid * 1024 + t; i < 20 * 4096; i += NBLK * 1024) H[i] = 0;
    }
    gridbar(0);

    // ---- S1: histogram of top-12 key bits ----
    {
        unsigned int* h = (unsigned int*)smem_raw;
        for (int ci = bid; ci < 136; ci += NBLK) {
            int n, l, c;
            chunk_map(ci, n, l, c);
            int p = n * NLVL + l;
            int HWA = hwa_of(l), n4 = HWA >> 2;
            int s4 = c * 2048;
            const float4* base = (const float4*)(P.logit[l] + (size_t)n * HWA);
            for (int b = t; b < 4096; b += 1024) h[b] = 0;
            __syncthreads();
            int i0 = s4 + t, i1 = s4 + 1024 + t;
            float4 v0, v1;
            if (i0 < n4) v0 = base[i0];
            if (i1 < n4) v1 = base[i1];
            if (i0 < n4) {
                atomicAdd(&h[fkey(v0.x) >> 20], 1u);
                atomicAdd(&h[fkey(v0.y) >> 20], 1u);
                atomicAdd(&h[fkey(v0.z) >> 20], 1u);
                atomicAdd(&h[fkey(v0.w) >> 20], 1u);
            }
            if (i1 < n4) {
                atomicAdd(&h[fkey(v1.x) >> 20], 1u);
                atomicAdd(&h[fkey(v1.y) >> 20], 1u);
                atomicAdd(&h[fkey(v1.z) >> 20], 1u);
                atomicAdd(&h[fkey(v1.w) >> 20], 1u);
            }
            __syncthreads();
            for (int b = t; b < 4096; b += 1024) {
                unsigned int cc = h[b];
                if (cc) atomicAdd(&g_hist[p][b], cc);
            }
            __syncthreads();
        }
    }
    gridbar(1);

    // ---- S2: threshold bin (20 blocks) ----
    if (bid < 20) {
        int p = bid, l = p % NLVL;
        unsigned int loc[4], s = 0;
#pragma unroll
        for (int q = 0; q < 4; q++) {
            loc[q] = g_hist[p][4095 - (t * 4 + q)];
            s += loc[q];
        }
        int tot;
        int ex = scan1024((int)s, &tot, sw);
        unsigned int target = (unsigned int)k_of(l);
        if ((unsigned)ex < target && (unsigned)ex + s >= target) {
            unsigned int cum = (unsigned)ex;
#pragma unroll
            for (int q = 0; q < 4; q++) {
                if (cum + loc[q] >= target) {
                    g_b1[p] = 4095u - (unsigned int)(t * 4 + q);
                    g_cnt[p] = 0u;
                    break;
                }
                cum += loc[q];
            }
        }
    }
    gridbar(2);

    // ---- S3: collect candidates (L2-hot) ----
    {
        for (int ci = bid; ci < 136; ci += NBLK) {
            int n, l, c;
            chunk_map(ci, n, l, c);
            int p = n * NLVL + l;
            int HWA = hwa_of(l), n4 = HWA >> 2;
            int s4 = c * 2048;
            unsigned int b1 = g_b1[p];
            const float4* base = (const float4*)(P.logit[l] + (size_t)n * HWA);
            int idx[2] = {s4 + t, s4 + 1024 + t};
            float4 v[2];
#pragma unroll
            for (int q = 0; q < 2; q++)
                if (idx[q] < n4) v[q] = base[idx[q]];
#pragma unroll
            for (int q = 0; q < 2; q++) {
                if (idx[q] < n4) {
                    float vv[4] = {v[q].x, v[q].y, v[q].z, v[q].w};
#pragma unroll
                    for (int e = 0; e < 4; e++) {
                        unsigned int key = fkey(vv[e]);
                        if ((key >> 20) >= b1) {
                            unsigned int pos = atomicAdd(&g_cnt[p], 1u);
                            if (pos < 8192u) {
                                int j = 4 * idx[q] + e;
                                g_cand[p][pos] =
                                    ((unsigned long long)key << 32) |
                                    (unsigned int)(~(unsigned int)j);
                            }
                        }
                    }
                }
            }
        }
    }
    gridbar(3);

    // ---- S4: sort + decode + per-level partition (20 blocks) ----
    if (bid < 20) {
        unsigned long long* sh = (unsigned long long*)smem_raw;
        int p = bid, n = p / NLVL, l = p % NLVL, k = k_of(l);
        int HWA = hwa_of(l), off = l * 1000;
        unsigned int cnt = min(g_cnt[p], 8192u);
        int size = 1024;
        while (size < (int)cnt) size <<= 1;
        for (int i = t; i < size; i += 1024)
            sh[i] = (i < (int)cnt) ? ~g_cand[p][i] : ~0ULL;
        for (int s = 2; s <= size; s <<= 1) {
            for (int st = s >> 1; st > 0; st >>= 1) {
                __syncthreads();
                int half = size >> 1;
                for (int tt = t; tt < half; tt += 1024) {
                    int a = 2 * tt - (tt & (st - 1));
                    int b = a + st;
                    bool asc = ((a & s) == 0);
                    unsigned long long x = sh[a], y = sh[b];
                    if ((x > y) == asc) { sh[a] = y; sh[b] = x; }
                }
            }
        }
        __syncthreads();

        int flag = 0;
        unsigned long long c = 0;
        if (t < k) {
            unsigned long long cc = ~sh[t];
            unsigned int key = (unsigned int)(cc >> 32);
            int j = (int)(~(unsigned int)cc);
            int m = off + t;
            const float* a = P.anch[l] + 4 * (size_t)j;
            const float* d = P.delta[l] + 4 * ((size_t)n * HWA + j);
            float ax1 = a[0], ay1 = a[1], ax2 = a[2], ay2 = a[3];
            float wa = __fsub_rn(ax2, ax1), ha = __fsub_rn(ay2, ay1);
            float cxa = __fadd_rn(ax1, __fmul_rn(0.5f, wa));
            float cya = __fadd_rn(ay1, __fmul_rn(0.5f, ha));
            float dx = d[0], dy = d[1], dw = d[2], dh = d[3];
            dw = fminf(dw, SCLAMP);
            dh = fminf(dh, SCLAMP);
            float cx = __fadd_rn(__fmul_rn(dx, wa), cxa);
            float cy = __fadd_rn(__fmul_rn(dy, ha), cya);
            float w = __fmul_rn(wa, expf(dw));
            float h = __fmul_rn(ha, expf(dh));
            float x1 = __fsub_rn(cx, __fmul_rn(0.5f, w));
            float y1 = __fsub_rn(cy, __fmul_rn(0.5f, h));
            float x2 = __fadd_rn(cx, __fmul_rn(0.5f, w));
            float y2 = __fadd_rn(cy, __fmul_rn(0.5f, h));
            x1 = fminf(fmaxf(x1, 0.f), 1024.f);
            y1 = fminf(fmaxf(y1, 0.f), 1024.f);
            x2 = fminf(fmaxf(x2, 0.f), 1024.f);
            y2 = fminf(fmaxf(y2, 0.f), 1024.f);
            float ww = __fsub_rn(x2, x1), hh = __fsub_rn(y2, y1);
            bool valid = (ww > 0.f) && (hh > 0.f);
            float sc = valid ? unkey(key) : NEGV;
            g_boxes[n][m][0] = x1;
            g_boxes[n][m][1] = y1;
            g_boxes[n][m][2] = x2;
            g_boxes[n][m][3] = y2;
            g_valid[n][m] = valid ? 1 : 0;
            g_fscore[n][m] = sc;
            flag = valid ? 1 : 0;
            c = ((unsigned long long)(~fkey(sc)) << 32) | (unsigned int)m;
        }
        int tot;
        int r = scan1024(flag, &tot, sw);
        if (t < k) g_comp[n][off + (flag ? r : tot + (t - r))] = c;
    }
    gridbar(4);

    // ---- S5: IoU mask tiles (items 0..303) + merge ranks (items 304..323) ----
    {
        for (int item = bid; item < 324; item += NBLK) {
            if (item < 304) {
                int n = item / 76, r = item % 76, l, tile;
                if (r < 64) { l = r >> 4; tile = r & 15; }
                else { l = 4; tile = r - 64; }
                int p = n * NLVL + l, k = k_of(l), off = l * 1000;
                float* sx1 = (float*)smem_raw;
                float* sy1 = sx1 + 1024;
                float* sx2 = sx1 + 2048;
                float* sy2 = sx1 + 3072;
                float* sar = sx1 + 4096;
                float offc = (float)l * 2048.0f;
                for (int i = t; i < k; i += 1024) {
                    float a = __fadd_rn(g_boxes[n][off + i][0], offc);
                    float b = __fadd_rn(g_boxes[n][off + i][1], offc);
                    float c2 = __fadd_rn(g_boxes[n][off + i][2], offc);
                    float d = __fadd_rn(g_boxes[n][off + i][3], offc);
                    sx1[i] = a; sy1[i] = b; sx2[i] = c2; sy2[i] = d;
                    sar[i] = __fmul_rn(__fsub_rn(c2, a), __fsub_rn(d, b));
                }
                __syncthreads();
                int i = tile * 64 + (t >> 4), w = t & 15;
                if (i < k) {
                    float ax1 = sx1[i], ay1 = sy1[i], ax2 = sx2[i],
                          ay2 = sy2[i], aa = sar[i];
                    int j0 = w * 64;
                    unsigned long long bits = 0;
                    if (j0 < k) {
                        int jend = min(j0 + 64, k);
                        for (int j = max(j0, i + 1); j < jend; j++) {
                            float w_ = __fsub_rn(fminf(ax2, sx2[j]),
                                                 fmaxf(ax1, sx1[j]));
                            if (w_ > 0.f) {
                                float h_ = __fsub_rn(fminf(ay2, sy2[j]),
                                                     fmaxf(ay1, sy1[j]));
                                if (h_ > 0.f) {
                                    float inter = __fmul_rn(w_, h_);
                                    float den = __fadd_rn(
                                        __fsub_rn(__fadd_rn(aa, sar[j]), inter),
                                        1e-9f);
                                    if (__fdiv_rn(inter, den) > NMS_THR)
                                        bits |= 1ULL << (j - j0);
                                }
                            }
                        }
                    }
                    g_mask[p][i][w] = bits;
                }
                __syncthreads();
            } else {
                int p = item - 304, n = p / NLVL, l = p % NLVL, k = k_of(l);
                int off = l * 1000;
                unsigned long long* sc = (unsigned long long*)smem_raw;
                for (int e = t; e < MTOT; e += 1024) sc[e] = g_comp[n][e];
                __syncthreads();
                if (t < k) {
                    unsigned long long c = sc[off + t];
                    int rank = t;
#pragma unroll
                    for (int l2 = 0; l2 < NLVL; l2++) {
                        if (l2 == l) continue;
                        int bse = l2 * 1000, len = k_of(l2);
                        int lo = 0, hi = len;
                        while (lo < hi) {
                            int mid = (lo + hi) >> 1;
                            if (sc[bse + mid] < c) lo = mid + 1;
                            else hi = mid;
                        }
                        rank += lo;
                    }
                    g_permF[n][rank] = (int)(unsigned int)(c & 0xFFFFFFFFULL);
                }
                __syncthreads();
            }
        }
    }
    gridbar(5);

    // ---- S6: serial greedy sweep (20 warps) ----
    if (bid < 20 && t < 32) {
        int p = bid, n = p / NLVL, l = p % NLVL, k = k_of(l), off = l * 1000;
        int lane = t;
        unsigned long long removedown = 0;
        unsigned long long cur = 0;
        unsigned long long bufA[8], bufB[8];
        int nspan = (k + 63) >> 6;
#pragma unroll
        for (int q = 0; q < 8; q++)
            bufA[q] = (lane < 16 && q < k) ? g_mask[p][q][lane] : 0ULL;
        for (int s = 0; s < nspan; s++) {
            int base = s * 64;
            bool v0 = (base + lane) < k && g_valid[n][off + base + lane];
            bool v1 =
                (base + 32 + lane) < k && g_valid[n][off + base + 32 + lane];
            unsigned int m0 = __ballot_sync(0xFFFFFFFFu, v0);
            unsigned int m1 = __ballot_sync(0xFFFFFFFFu, v1);
            unsigned long long validw = ((unsigned long long)m1 << 32) | m0;
            unsigned long long keptw = 0;
            for (int sub = 0; sub < 8; sub++) {
                int nb = base + sub * 8 + 8;
#pragma unroll
                for (int q = 0; q < 8; q++) {
                    int ni = nb + q;
                    bufB[q] = (lane < 16 && ni < k) ? g_mask[p][ni][lane] : 0ULL;
                }
#pragma unroll
                for (int q = 0; q < 8; q++) {
                    int bit = sub * 8 + q;
                    unsigned long long rc = __shfl_sync(0xFFFFFFFFu, bufA[q], s);
                    bool keep =
                        ((validw >> bit) & 1ULL) && !((cur >> bit) & 1ULL);
                    if (keep) {
                        cur |= rc;
                        removedown |= bufA[q];
                        keptw |= 1ULL << bit;
                    }
                }
#pragma unroll
                for (int q = 0; q < 8; q++) bufA[q] = bufB[q];
            }
            if (lane == 0) g_keptw[p][s] = keptw;
            cur = __shfl_sync(0xFFFFFFFFu, removedown, min(s + 1, 15));
        }
        for (int s = nspan + lane; s < 16; s += 32) g_keptw[p][s] = 0ULL;
    }
    gridbar(6);

    // ---- S7: stable partition by kept flag + emit (4 blocks) ----
    if (bid < 4) {
        int n = bid;
        int f[5], mloc[5], ls = 0;
#pragma unroll
        for (int q = 0; q < 5; q++) {
            int r = t * 5 + q;
            if (r < MTOT) {
                int m = g_permF[n][r];
                mloc[q] = m;
                int lvl = m / 1000, mm = m % 1000;
                f[q] = (int)((g_keptw[n * NLVL + lvl][mm >> 6] >> (mm & 63)) &
                             1ULL);
            } else {
                mloc[q] = 0;
                f[q] = 0;
            }
            ls += f[q];
        }
        int tot;
        int kr = scan1024(ls, &tot, sw);
#pragma unroll
        for (int q = 0; q < 5; q++) {
            int r = t * 5 + q;
            if (r < MTOT) {
                int pos = f[q] ? kr : tot + (r - kr);
                if (pos < 1000) {
                    int m = mloc[q];
                    out[((size_t)n * 1000 + pos) * 4 + 0] = g_boxes[n][m][0];
                    out[((size_t)n * 1000 + pos) * 4 + 1] = g_boxes[n][m][1];
                    out[((size_t)n * 1000 + pos) * 4 + 2] = g_boxes[n][m][2];
                    out[((size_t)n * 1000 + pos) * 4 + 3] = g_boxes[n][m][3];
                    out[NIMG * 1000 * 4 + (size_t)n * 1000 + pos] =
                        f[q] ? g_fscore[n][m] : NEGV;
                }
                kr += f[q];
            }
        }
    }
}

// ---------------- host launcher ----------------
extern "C" void kernel_launch(void* const* d_in, const int* in_sizes, int n_in,
                              void* d_out, int out_size) {
    Ptrs P;
    bool interleaved = (n_in >= 2 && in_sizes[1] == 3145728);
    for (int l = 0; l < NLVL; l++) {
        if (interleaved) {
            P.logit[l] = (const float*)d_in[3 * l + 0];
            P.delta[l] = (const float*)d_in[3 * l + 1];
            P.anch[l] = (const float*)d_in[3 * l + 2];
        } else {
            P.logit[l] = (const float*)d_in[l];
            P.delta[l] = (const float*)d_in[5 + l];
            P.anch[l] = (const float*)d_in[10 + l];
        }
    }
    float* out = (float*)d_out;

    cudaFuncSetAttribute(k_all, cudaFuncAttributeMaxDynamicSharedMemorySize,
                         65536);
    k_all<<<NBLK, 1024, 65536>>>(P, out);
}

// round 6
// speedup vs baseline: 1.6167x; 1.4913x over previous
#include <cuda_runtime.h>
#include <cstdint>

#define NIMG 4
#define NLVL 5
#define MTOT 4768
#define NEGV (-1e9f)
#define NMS_THR 0.7f
#define SCLAMP 4.135166556742356f
#define NBLK 148

__device__ __forceinline__ int hwa_of(int l) { return 196608 >> (2 * l); }
__device__ __forceinline__ int k_of(int l) { return (l == 4) ? 768 : 1000; }

__device__ __forceinline__ unsigned int fkey(float f) {
    unsigned int u = __float_as_uint(f);
    return (u & 0x80000000u) ? ~u : (u | 0x80000000u);
}
__device__ __forceinline__ float unkey(unsigned int key) {
    return __uint_as_float((key & 0x80000000u) ? (key & 0x7FFFFFFFu) : ~key);
}

// ---------------- scratch (device globals; no allocations) ----------------
__device__ unsigned int g_hist[20][4096];
__device__ unsigned int g_cnt[20];
__device__ unsigned int g_b1[20];
__device__ unsigned long long g_cand[20][8192];
__device__ float g_boxes[NIMG][MTOT][4];
__device__ float g_fscore[NIMG][MTOT];
__device__ unsigned char g_valid[NIMG][MTOT];
__device__ unsigned long long g_comp[NIMG][MTOT];
__device__ unsigned long long g_keptw[20][16];
__device__ unsigned long long g_mask[20][1000][16];
__device__ int g_permF[NIMG][MTOT];
__device__ unsigned long long g_barcnt[8];  // monotonic; NEVER reset (replay-safe)

struct Ptrs {
    const float* logit[NLVL];
    const float* delta[NLVL];
    const float* anch[NLVL];
};

// ---------------- replay-safe grid barrier (monotonic tickets) ------------
__device__ __forceinline__ void gridbar(int b) {
    __syncthreads();
    if (threadIdx.x == 0) {
        __threadfence();
        unsigned long long ticket = atomicAdd(&g_barcnt[b], 1ULL);
        unsigned long long target =
            (ticket / (unsigned long long)NBLK + 1ULL) * (unsigned long long)NBLK;
        while (((volatile unsigned long long*)g_barcnt)[b] < target) {
            __nanosleep(64);
        }
        __threadfence();
    }
    __syncthreads();
}

// ---------------- block scan helper (1024 threads, exclusive) -------------
__device__ __forceinline__ int scan1024(int v, int* total, int* sw) {
    __syncthreads();
    int lane = threadIdx.x & 31, w = threadIdx.x >> 5;
    int x = v;
#pragma unroll
    for (int d = 1; d < 32; d <<= 1) {
        int y = __shfl_up_sync(0xFFFFFFFFu, x, d);
        if (lane >= d) x += y;
    }
    if (lane == 31) sw[w] = x;
    __syncthreads();
    if (w == 0) {
        int ws = sw[lane], xx = ws;
#pragma unroll
        for (int d = 1; d < 32; d <<= 1) {
            int y = __shfl_up_sync(0xFFFFFFFFu, xx, d);
            if (lane >= d) xx += y;
        }
        sw[lane] = xx - ws;
        if (lane == 31) sw[32] = xx;
    }
    __syncthreads();
    *total = sw[32];
    return x - v + sw[w];
}

// chunk index -> (n, l, c); 34 chunks of 8192 elems per image, 136 total
__device__ __forceinline__ void chunk_map(int ci, int& n, int& l, int& c) {
    n = ci / 34;
    int r = ci % 34;
    if (r < 24) { l = 0; c = r; }
    else if (r < 30) { l = 1; c = r - 24; }
    else if (r < 32) { l = 2; c = r - 30; }
    else if (r < 33) { l = 3; c = 0; }
    else { l = 4; c = 0; }
}

// ============================ the one kernel ==============================
__global__ void __launch_bounds__(1024, 1) k_all(Ptrs P, float* out) {
    extern __shared__ unsigned char smem_raw[];
    __shared__ int sw[33];
    int bid = blockIdx.x, t = threadIdx.x;

    // ---- S0: zero global histograms ----
    {
        unsigned int* H = (unsigned int*)g_hist;
        for (int i = bid * 1024 + t; i < 20 * 4096; i += NBLK * 1024) H[i] = 0;
    }
    gridbar(0);

    // ---- S1: histogram of top-12 key bits ----
    {
        unsigned int* h = (unsigned int*)smem_raw;
        for (int ci = bid; ci < 136; ci += NBLK) {
            int n, l, c;
            chunk_map(ci, n, l, c);
            int p = n * NLVL + l;
            int HWA = hwa_of(l), n4 = HWA >> 2;
            int s4 = c * 2048;
            const float4* base = (const float4*)(P.logit[l] + (size_t)n * HWA);
            for (int b = t; b < 4096; b += 1024) h[b] = 0;
            __syncthreads();
            int i0 = s4 + t, i1 = s4 + 1024 + t;
            float4 v0, v1;
            if (i0 < n4) v0 = base[i0];
            if (i1 < n4) v1 = base[i1];
            if (i0 < n4) {
                atomicAdd(&h[fkey(v0.x) >> 20], 1u);
                atomicAdd(&h[fkey(v0.y) >> 20], 1u);
                atomicAdd(&h[fkey(v0.z) >> 20], 1u);
                atomicAdd(&h[fkey(v0.w) >> 20], 1u);
            }
            if (i1 < n4) {
                atomicAdd(&h[fkey(v1.x) >> 20], 1u);
                atomicAdd(&h[fkey(v1.y) >> 20], 1u);
                atomicAdd(&h[fkey(v1.z) >> 20], 1u);
                atomicAdd(&h[fkey(v1.w) >> 20], 1u);
            }
            __syncthreads();
            for (int b = t; b < 4096; b += 1024) {
                unsigned int cc = h[b];
                if (cc) atomicAdd(&g_hist[p][b], cc);
            }
            __syncthreads();
        }
    }
    gridbar(1);

    // ---- S2: threshold bin (20 blocks) ----
    if (bid < 20) {
        int p = bid, l = p % NLVL;
        unsigned int loc[4], s = 0;
#pragma unroll
        for (int q = 0; q < 4; q++) {
            loc[q] = g_hist[p][4095 - (t * 4 + q)];
            s += loc[q];
        }
        int tot;
        int ex = scan1024((int)s, &tot, sw);
        unsigned int target = (unsigned int)k_of(l);
        if ((unsigned)ex < target && (unsigned)ex + s >= target) {
            unsigned int cum = (unsigned)ex;
#pragma unroll
            for (int q = 0; q < 4; q++) {
                if (cum + loc[q] >= target) {
                    g_b1[p] = 4095u - (unsigned int)(t * 4 + q);
                    g_cnt[p] = 0u;
                    break;
                }
                cum += loc[q];
            }
        }
    }
    gridbar(2);

    // ---- S3: collect candidates (L2-hot) ----
    {
        for (int ci = bid; ci < 136; ci += NBLK) {
            int n, l, c;
            chunk_map(ci, n, l, c);
            int p = n * NLVL + l;
            int HWA = hwa_of(l), n4 = HWA >> 2;
            int s4 = c * 2048;
            unsigned int b1 = g_b1[p];
            const float4* base = (const float4*)(P.logit[l] + (size_t)n * HWA);
            int idx[2] = {s4 + t, s4 + 1024 + t};
            float4 v[2];
#pragma unroll
            for (int q = 0; q < 2; q++)
                if (idx[q] < n4) v[q] = base[idx[q]];
#pragma unroll
            for (int q = 0; q < 2; q++) {
                if (idx[q] < n4) {
                    float vv[4] = {v[q].x, v[q].y, v[q].z, v[q].w};
#pragma unroll
                    for (int e = 0; e < 4; e++) {
                        unsigned int key = fkey(vv[e]);
                        if ((key >> 20) >= b1) {
                            unsigned int pos = atomicAdd(&g_cnt[p], 1u);
                            if (pos < 8192u) {
                                int j = 4 * idx[q] + e;
                                g_cand[p][pos] =
                                    ((unsigned long long)key << 32) |
                                    (unsigned int)(~(unsigned int)j);
                            }
                        }
                    }
                }
            }
        }
    }
    gridbar(3);

    // ---- S4: sort + decode + per-level partition (20 blocks) ----
    if (bid < 20) {
        unsigned long long* sh = (unsigned long long*)smem_raw;
        int p = bid, n = p / NLVL, l = p % NLVL, k = k_of(l);
        int HWA = hwa_of(l), off = l * 1000;
        unsigned int cnt = min(g_cnt[p], 8192u);
        int size = 1024;
        while (size < (int)cnt) size <<= 1;
        for (int i = t; i < size; i += 1024)
            sh[i] = (i < (int)cnt) ? ~g_cand[p][i] : ~0ULL;
        for (int s = 2; s <= size; s <<= 1) {
            for (int st = s >> 1; st > 0; st >>= 1) {
                __syncthreads();
                int half = size >> 1;
                for (int tt = t; tt < half; tt += 1024) {
                    int a = 2 * tt - (tt & (st - 1));
                    int b = a + st;
                    bool asc = ((a & s) == 0);
                    unsigned long long x = sh[a], y = sh[b];
                    if ((x > y) == asc) { sh[a] = y; sh[b] = x; }
                }
            }
        }
        __syncthreads();

        int flag = 0;
        unsigned long long c = 0;
        if (t < k) {
            unsigned long long cc = ~sh[t];
            unsigned int key = (unsigned int)(cc >> 32);
            int j = (int)(~(unsigned int)cc);
            int m = off + t;
            const float* a = P.anch[l] + 4 * (size_t)j;
            const float* d = P.delta[l] + 4 * ((size_t)n * HWA + j);
            float ax1 = a[0], ay1 = a[1], ax2 = a[2], ay2 = a[3];
            float wa = __fsub_rn(ax2, ax1), ha = __fsub_rn(ay2, ay1);
            float cxa = __fadd_rn(ax1, __fmul_rn(0.5f, wa));
            float cya = __fadd_rn(ay1, __fmul_rn(0.5f, ha));
            float dx = d[0], dy = d[1], dw = d[2], dh = d[3];
            dw = fminf(dw, SCLAMP);
            dh = fminf(dh, SCLAMP);
            float cx = __fadd_rn(__fmul_rn(dx, wa), cxa);
            float cy = __fadd_rn(__fmul_rn(dy, ha), cya);
            float w = __fmul_rn(wa, expf(dw));
            float h = __fmul_rn(ha, expf(dh));
            float x1 = __fsub_rn(cx, __fmul_rn(0.5f, w));
            float y1 = __fsub_rn(cy, __fmul_rn(0.5f, h));
            float x2 = __fadd_rn(cx, __fmul_rn(0.5f, w));
            float y2 = __fadd_rn(cy, __fmul_rn(0.5f, h));
            x1 = fminf(fmaxf(x1, 0.f), 1024.f);
            y1 = fminf(fmaxf(y1, 0.f), 1024.f);
            x2 = fminf(fmaxf(x2, 0.f), 1024.f);
            y2 = fminf(fmaxf(y2, 0.f), 1024.f);
            float ww = __fsub_rn(x2, x1), hh = __fsub_rn(y2, y1);
            bool valid = (ww > 0.f) && (hh > 0.f);
            float sc = valid ? unkey(key) : NEGV;
            g_boxes[n][m][0] = x1;
            g_boxes[n][m][1] = y1;
            g_boxes[n][m][2] = x2;
            g_boxes[n][m][3] = y2;
            g_valid[n][m] = valid ? 1 : 0;
            g_fscore[n][m] = sc;
            flag = valid ? 1 : 0;
            c = ((unsigned long long)(~fkey(sc)) << 32) | (unsigned int)m;
        }
        int tot;
        int r = scan1024(flag, &tot, sw);
        if (t < k) g_comp[n][off + (flag ? r : tot + (t - r))] = c;
    }
    gridbar(4);

    // ---- S5: IoU mask (warp-per-row, lane-per-j; conflict-free)
    //          items 0..303: 64-row blocks; items 304..323: merge ranks ----
    {
        for (int item = bid; item < 324; item += NBLK) {
            if (item < 304) {
                int n = item / 76, r = item % 76, l, rowblk;
                if (r < 64) { l = r >> 4; rowblk = r & 15; }
                else { l = 4; rowblk = r - 64; }
                int p = n * NLVL + l, k = k_of(l), off = l * 1000;
                float4* sb = (float4*)smem_raw;          // [1024] boxes
                float* sar = (float*)(sb + 1024);        // [1024] areas
                float offc = (float)l * 2048.0f;
                const float4* gb = (const float4*)g_boxes[n];
                for (int i = t; i < k; i += 1024) {
                    float4 b = gb[off + i];
                    b.x = __fadd_rn(b.x, offc);
                    b.y = __fadd_rn(b.y, offc);
                    b.z = __fadd_rn(b.z, offc);
                    b.w = __fadd_rn(b.w, offc);
                    sb[i] = b;
                    sar[i] =
                        __fmul_rn(__fsub_rn(b.z, b.x), __fsub_rn(b.w, b.y));
                }
                __syncthreads();
                int wid = t >> 5, lane = t & 31;
#pragma unroll
                for (int rr = 0; rr < 2; rr++) {
                    int i = rowblk * 64 + wid * 2 + rr;
                    if (i < k) {
                        float4 bi = sb[i];
                        float aa = sar[i];
                        unsigned int* mrow = (unsigned int*)g_mask[p][i];
                        for (int ch = 0; ch < 32; ch++) {
                            unsigned int bits = 0;
                            // chunk has any j with i < j < k ?
                            if (ch * 32 < k && (ch + 1) * 32 > i + 1) {
                                int j = ch * 32 + lane;
                                bool sup = false;
                                if (j > i && j < k) {
                                    float4 bj = sb[j];
                                    float w_ = __fsub_rn(fminf(bi.z, bj.z),
                                                         fmaxf(bi.x, bj.x));
                                    float h_ = __fsub_rn(fminf(bi.w, bj.w),
                                                         fmaxf(bi.y, bj.y));
                                    if (w_ > 0.f && h_ > 0.f) {
                                        float inter = __fmul_rn(w_, h_);
                                        float den = __fadd_rn(
                                            __fsub_rn(__fadd_rn(aa, sar[j]),
                                                      inter),
                                            1e-9f);
                                        sup = __fdiv_rn(inter, den) > NMS_THR;
                                    }
                                }
                                bits = __ballot_sync(0xFFFFFFFFu, sup);
                            }
                            if (lane == 0) mrow[ch] = bits;
                        }
                    }
                }
                __syncthreads();
            } else {
                int p = item - 304, n = p / NLVL, l = p % NLVL, k = k_of(l);
                int off = l * 1000;
                unsigned long long* sc = (unsigned long long*)smem_raw;
                for (int e = t; e < MTOT; e += 1024) sc[e] = g_comp[n][e];
                __syncthreads();
                if (t < k) {
                    unsigned long long c = sc[off + t];
                    int rank = t;
#pragma unroll
                    for (int l2 = 0; l2 < NLVL; l2++) {
                        if (l2 == l) continue;
                        int bse = l2 * 1000, len = k_of(l2);
                        int lo = 0, hi = len;
                        while (lo < hi) {
                            int mid = (lo + hi) >> 1;
                            if (sc[bse + mid] < c) lo = mid + 1;
                            else hi = mid;
                        }
                        rank += lo;
                    }
                    g_permF[n][rank] = (int)(unsigned int)(c & 0xFFFFFFFFULL);
                }
                __syncthreads();
            }
        }
    }
    gridbar(5);

    // ---- S6: serial greedy sweep (20 warps) ----
    if (bid < 20 && t < 32) {
        int p = bid, n = p / NLVL, l = p % NLVL, k = k_of(l), off = l * 1000;
        int lane = t;
        unsigned long long removedown = 0;
        unsigned long long cur = 0;
        unsigned long long bufA[8], bufB[8];
        int nspan = (k + 63) >> 6;
#pragma unroll
        for (int q = 0; q < 8; q++)
            bufA[q] = (lane < 16 && q < k) ? g_mask[p][q][lane] : 0ULL;
        for (int s = 0; s < nspan; s++) {
            int base = s * 64;
            bool v0 = (base + lane) < k && g_valid[n][off + base + lane];
            bool v1 =
                (base + 32 + lane) < k && g_valid[n][off + base + 32 + lane];
            unsigned int m0 = __ballot_sync(0xFFFFFFFFu, v0);
            unsigned int m1 = __ballot_sync(0xFFFFFFFFu, v1);
            unsigned long long validw = ((unsigned long long)m1 << 32) | m0;
            unsigned long long keptw = 0;
            for (int sub = 0; sub < 8; sub++) {
                int nb = base + sub * 8 + 8;
#pragma unroll
                for (int q = 0; q < 8; q++) {
                    int ni = nb + q;
                    bufB[q] = (lane < 16 && ni < k) ? g_mask[p][ni][lane] : 0ULL;
                }
#pragma unroll
                for (int q = 0; q < 8; q++) {
                    int bit = sub * 8 + q;
                    unsigned long long rc = __shfl_sync(0xFFFFFFFFu, bufA[q], s);
                    bool keep =
                        ((validw >> bit) & 1ULL) && !((cur >> bit) & 1ULL);
                    if (keep) {
                        cur |= rc;
                        removedown |= bufA[q];
                        keptw |= 1ULL << bit;
                    }
                }
#pragma unroll
                for (int q = 0; q < 8; q++) bufA[q] = bufB[q];
            }
            if (lane == 0) g_keptw[p][s] = keptw;
            cur = __shfl_sync(0xFFFFFFFFu, removedown, min(s + 1, 15));
        }
        for (int s = nspan + lane; s < 16; s += 32) g_keptw[p][s] = 0ULL;
    }
    gridbar(6);

    // ---- S7: stable partition by kept flag + emit (4 blocks) ----
    if (bid < 4) {
        int n = bid;
        int f[5], mloc[5], ls = 0;
#pragma unroll
        for (int q = 0; q < 5; q++) {
            int r = t * 5 + q;
            if (r < MTOT) {
                int m = g_permF[n][r];
                mloc[q] = m;
                int lvl = m / 1000, mm = m % 1000;
                f[q] = (int)((g_keptw[n * NLVL + lvl][mm >> 6] >> (mm & 63)) &
                             1ULL);
            } else {
                mloc[q] = 0;
                f[q] = 0;
            }
            ls += f[q];
        }
        int tot;
        int kr = scan1024(ls, &tot, sw);
#pragma unroll
        for (int q = 0; q < 5; q++) {
            int r = t * 5 + q;
            if (r < MTOT) {
                int pos = f[q] ? kr : tot + (r - kr);
                if (pos < 1000) {
                    int m = mloc[q];
                    out[((size_t)n * 1000 + pos) * 4 + 0] = g_boxes[n][m][0];
                    out[((size_t)n * 1000 + pos) * 4 + 1] = g_boxes[n][m][1];
                    out[((size_t)n * 1000 + pos) * 4 + 2] = g_boxes[n][m][2];
                    out[((size_t)n * 1000 + pos) * 4 + 3] = g_boxes[n][m][3];
                    out[NIMG * 1000 * 4 + (size_t)n * 1000 + pos] =
                        f[q] ? g_fscore[n][m] : NEGV;
                }
                kr += f[q];
            }
        }
    }
}

// ---------------- host launcher ----------------
extern "C" void kernel_launch(void* const* d_in, const int* in_sizes, int n_in,
                              void* d_out, int out_size) {
    Ptrs P;
    bool interleaved = (n_in >= 2 && in_sizes[1] == 3145728);
    for (int l = 0; l < NLVL; l++) {
        if (interleaved) {
            P.logit[l] = (const float*)d_in[3 * l + 0];
            P.delta[l] = (const float*)d_in[3 * l + 1];
            P.anch[l] = (const float*)d_in[3 * l + 2];
        } else {
            P.logit[l] = (const float*)d_in[l];
            P.delta[l] = (const float*)d_in[5 + l];
            P.anch[l] = (const float*)d_in[10 + l];
        }
    }
    float* out = (float*)d_out;

    cudaFuncSetAttribute(k_all, cudaFuncAttributeMaxDynamicSharedMemorySize,
                         65536);
    k_all<<<NBLK, 1024, 65536>>>(P, out);
}